// round 1
// baseline (speedup 1.0000x reference)
#include <cuda_runtime.h>
#include <cuda_bf16.h>
#include <cstdint>

#define L 256
#define D 128
#define H 4
#define DH 32
#define TP 16
#define SCALING 0.17677669529663687f

// ---- scratch (static device globals; no runtime allocation) ----
__device__ float g_q[L * L * D];
__device__ float g_k[L * L * D];
__device__ float g_v[L * L * D];
__device__ float g_gate[L * L * D];
__device__ float g_att[L * L * D];
__device__ float g_biasT[H * L * L];   // [h][k][j]

// 8-wide GEMV inner loop: one row of x (smem, broadcast) times 8 columns of W.
__device__ __forceinline__ void gemv8(const float* __restrict__ xrow,
                                      const float* __restrict__ W,
                                      int c0, float* acc) {
#pragma unroll 4
    for (int d = 0; d < D; ++d) {
        float xv = xrow[d];
        float4 w0 = *reinterpret_cast<const float4*>(W + d * D + c0);
        float4 w1 = *reinterpret_cast<const float4*>(W + d * D + c0 + 4);
        acc[0] += xv * w0.x; acc[1] += xv * w0.y;
        acc[2] += xv * w0.z; acc[3] += xv * w0.w;
        acc[4] += xv * w1.x; acc[5] += xv * w1.y;
        acc[6] += xv * w1.z; acc[7] += xv * w1.w;
    }
}

// Kernel A: LayerNorm + Q/K/V/gate projections + attention bias (transposed store).
// Block = 256 threads handles TP=16 pair-positions.
__global__ void __launch_bounds__(256) proj_kernel(
    const float* __restrict__ pair,
    const float* __restrict__ gamma, const float* __restrict__ beta,
    const float* __restrict__ Wq, const float* __restrict__ Wk,
    const float* __restrict__ Wv, const float* __restrict__ Wb,
    const float* __restrict__ Wg, const float* __restrict__ bg)
{
    __shared__ float xs[TP][D];
    const int t = threadIdx.x;
    const int warp = t >> 5, lane = t & 31;
    const int p0 = blockIdx.x * TP;

    // ---- LayerNorm: warp w handles rows 2w, 2w+1 ----
    float4 gv = reinterpret_cast<const float4*>(gamma)[lane];
    float4 bv = reinterpret_cast<const float4*>(beta)[lane];
#pragma unroll
    for (int rr = 0; rr < 2; ++rr) {
        int r = warp * 2 + rr;
        float4 x = reinterpret_cast<const float4*>(pair + (size_t)(p0 + r) * D)[lane];
        float s  = x.x + x.y + x.z + x.w;
        float s2 = x.x * x.x + x.y * x.y + x.z * x.z + x.w * x.w;
#pragma unroll
        for (int o = 16; o > 0; o >>= 1) {
            s  += __shfl_xor_sync(0xffffffffu, s,  o);
            s2 += __shfl_xor_sync(0xffffffffu, s2, o);
        }
        float mu  = s * (1.0f / 128.0f);
        float var = s2 * (1.0f / 128.0f) - mu * mu;
        float rs  = rsqrtf(var + 1e-5f);
        float4 xn;
        xn.x = (x.x - mu) * rs * gv.x + bv.x;
        xn.y = (x.y - mu) * rs * gv.y + bv.y;
        xn.z = (x.z - mu) * rs * gv.z + bv.z;
        xn.w = (x.w - mu) * rs * gv.w + bv.w;
        reinterpret_cast<float4*>(&xs[r][0])[lane] = xn;
    }
    __syncthreads();

    // ---- projections: thread -> (row r, 8 columns starting at c0) ----
    const int r  = t >> 4;
    const int c0 = (t & 15) * 8;
    const size_t prow = (size_t)(p0 + r) * D + c0;
    const float* xrow = &xs[r][0];

    {   // Q (scaled)
        float acc[8] = {0, 0, 0, 0, 0, 0, 0, 0};
        gemv8(xrow, Wq, c0, acc);
        float4 o0 = {acc[0] * SCALING, acc[1] * SCALING, acc[2] * SCALING, acc[3] * SCALING};
        float4 o1 = {acc[4] * SCALING, acc[5] * SCALING, acc[6] * SCALING, acc[7] * SCALING};
        *reinterpret_cast<float4*>(g_q + prow)     = o0;
        *reinterpret_cast<float4*>(g_q + prow + 4) = o1;
    }
    {   // K
        float acc[8] = {0, 0, 0, 0, 0, 0, 0, 0};
        gemv8(xrow, Wk, c0, acc);
        *reinterpret_cast<float4*>(g_k + prow)     = make_float4(acc[0], acc[1], acc[2], acc[3]);
        *reinterpret_cast<float4*>(g_k + prow + 4) = make_float4(acc[4], acc[5], acc[6], acc[7]);
    }
    {   // V
        float acc[8] = {0, 0, 0, 0, 0, 0, 0, 0};
        gemv8(xrow, Wv, c0, acc);
        *reinterpret_cast<float4*>(g_v + prow)     = make_float4(acc[0], acc[1], acc[2], acc[3]);
        *reinterpret_cast<float4*>(g_v + prow + 4) = make_float4(acc[4], acc[5], acc[6], acc[7]);
    }
    {   // gate = sigmoid(x@Wg + bg)
        float acc[8] = {0, 0, 0, 0, 0, 0, 0, 0};
        gemv8(xrow, Wg, c0, acc);
        float4 o0, o1;
        float z;
        z = acc[0] + bg[c0 + 0]; o0.x = 1.0f / (1.0f + __expf(-z));
        z = acc[1] + bg[c0 + 1]; o0.y = 1.0f / (1.0f + __expf(-z));
        z = acc[2] + bg[c0 + 2]; o0.z = 1.0f / (1.0f + __expf(-z));
        z = acc[3] + bg[c0 + 3]; o0.w = 1.0f / (1.0f + __expf(-z));
        z = acc[4] + bg[c0 + 4]; o1.x = 1.0f / (1.0f + __expf(-z));
        z = acc[5] + bg[c0 + 5]; o1.y = 1.0f / (1.0f + __expf(-z));
        z = acc[6] + bg[c0 + 6]; o1.z = 1.0f / (1.0f + __expf(-z));
        z = acc[7] + bg[c0 + 7]; o1.w = 1.0f / (1.0f + __expf(-z));
        *reinterpret_cast<float4*>(g_gate + prow)     = o0;
        *reinterpret_cast<float4*>(g_gate + prow + 4) = o1;
    }

    // ---- bias = x @ Wb, stored transposed as [h][k][j] ----
    if (t < 64) {
        int rb = t >> 2;      // row 0..15
        int hb = t & 3;       // head
        float acc = 0.0f;
#pragma unroll 4
        for (int d = 0; d < D; ++d) acc += xs[rb][d] * Wb[d * H + hb];
        int p = p0 + rb;
        int jj = p >> 8;      // first pair index (j for bias)
        int kk = p & 255;     // second pair index (k for bias)
        g_biasT[((size_t)hb * L + kk) * L + jj] = acc;
    }
}

// Kernel B: attention for one (row i, head h) per block; thread = query index j.
// K/V staged in dynamic smem (64 KB), read via broadcast float4 LDS.
// No max-subtraction: |scores| << 1 by construction (0.02-scale weights).
__global__ void __launch_bounds__(256) attn_kernel()
{
    extern __shared__ float sm[];
    float* sK = sm;            // [256][32]
    float* sV = sm + L * DH;   // [256][32]

    const int i = blockIdx.x;
    const int h = blockIdx.y;
    const int t = threadIdx.x;          // j

    const size_t base = (size_t)i * L * D + (size_t)h * DH;
    // stage K and V rows for this (i, h)
    for (int idx = t; idx < L * DH / 4; idx += 256) {
        int k  = idx >> 3;
        int u  = idx & 7;
        reinterpret_cast<float4*>(sK + k * DH)[u] =
            reinterpret_cast<const float4*>(g_k + base + (size_t)k * D)[u];
        reinterpret_cast<float4*>(sV + k * DH)[u] =
            reinterpret_cast<const float4*>(g_v + base + (size_t)k * D)[u];
    }
    __syncthreads();

    // load q[j] into registers
    float4 qr[8];
    const size_t qbase = base + (size_t)t * D;
#pragma unroll
    for (int u = 0; u < 8; ++u)
        qr[u] = reinterpret_cast<const float4*>(g_q + qbase)[u];

    const float* biasp = g_biasT + (size_t)h * L * L + t;   // + k*L per step

    float4 out[8];
#pragma unroll
    for (int u = 0; u < 8; ++u) out[u] = make_float4(0.f, 0.f, 0.f, 0.f);
    float ssum = 0.0f;

#pragma unroll 2
    for (int k = 0; k < L; ++k) {
        const float4* kr = reinterpret_cast<const float4*>(sK + k * DH);
        float s = 0.0f;
#pragma unroll
        for (int u = 0; u < 8; ++u) {
            float4 kv = kr[u];
            s += qr[u].x * kv.x + qr[u].y * kv.y + qr[u].z * kv.z + qr[u].w * kv.w;
        }
        s += biasp[(size_t)k * L];          // coalesced across j
        float pw = __expf(s);
        ssum += pw;
        const float4* vr = reinterpret_cast<const float4*>(sV + k * DH);
#pragma unroll
        for (int u = 0; u < 8; ++u) {
            float4 vv = vr[u];
            out[u].x += pw * vv.x; out[u].y += pw * vv.y;
            out[u].z += pw * vv.z; out[u].w += pw * vv.w;
        }
    }

    float inv = 1.0f / ssum;
    float* op = g_att + qbase;
#pragma unroll
    for (int u = 0; u < 8; ++u) {
        float4 o = out[u];
        o.x *= inv; o.y *= inv; o.z *= inv; o.w *= inv;
        reinterpret_cast<float4*>(op)[u] = o;
    }
}

// Kernel C: out = (gate * att) @ Wo + bo
__global__ void __launch_bounds__(256) epi_kernel(
    const float* __restrict__ Wo, const float* __restrict__ bo,
    float* __restrict__ out)
{
    __shared__ float ys[TP][D];
    const int t = threadIdx.x;
    const int p0 = blockIdx.x * TP;

#pragma unroll
    for (int u = 0; u < 2; ++u) {
        int idx = u * 256 + t;           // float4 units over 16x128
        int r = idx >> 5, q = idx & 31;
        size_t off = (size_t)(p0 + r) * D + q * 4;
        float4 g = *reinterpret_cast<const float4*>(g_gate + off);
        float4 a = *reinterpret_cast<const float4*>(g_att + off);
        float4 y = {g.x * a.x, g.y * a.y, g.z * a.z, g.w * a.w};
        reinterpret_cast<float4*>(&ys[r][0])[q] = y;
    }
    __syncthreads();

    const int r  = t >> 4;
    const int c0 = (t & 15) * 8;
    float acc[8] = {0, 0, 0, 0, 0, 0, 0, 0};
    gemv8(&ys[r][0], Wo, c0, acc);

    size_t prow = (size_t)(p0 + r) * D + c0;
    float4 o0 = {acc[0] + bo[c0 + 0], acc[1] + bo[c0 + 1],
                 acc[2] + bo[c0 + 2], acc[3] + bo[c0 + 3]};
    float4 o1 = {acc[4] + bo[c0 + 4], acc[5] + bo[c0 + 5],
                 acc[6] + bo[c0 + 6], acc[7] + bo[c0 + 7]};
    *reinterpret_cast<float4*>(out + prow)     = o0;
    *reinterpret_cast<float4*>(out + prow + 4) = o1;
}

extern "C" void kernel_launch(void* const* d_in, const int* in_sizes, int n_in,
                              void* d_out, int out_size)
{
    const float* pair  = (const float*)d_in[0];
    const float* gamma = (const float*)d_in[1];
    const float* beta  = (const float*)d_in[2];
    const float* Wq    = (const float*)d_in[3];
    const float* Wk    = (const float*)d_in[4];
    const float* Wv    = (const float*)d_in[5];
    const float* Wb    = (const float*)d_in[6];
    const float* Wg    = (const float*)d_in[7];
    const float* bg    = (const float*)d_in[8];
    const float* Wo    = (const float*)d_in[9];
    const float* bo    = (const float*)d_in[10];
    float* out = (float*)d_out;

    // 64 KB dynamic smem for K+V tiles (idempotent; not a stream op).
    cudaFuncSetAttribute(attn_kernel, cudaFuncAttributeMaxDynamicSharedMemorySize,
                         2 * L * DH * (int)sizeof(float));

    proj_kernel<<<(L * L) / TP, 256>>>(pair, gamma, beta, Wq, Wk, Wv, Wb, Wg, bg);
    attn_kernel<<<dim3(L, H), 256, 2 * L * DH * sizeof(float)>>>();
    epi_kernel<<<(L * L) / TP, 256>>>(Wo, bo, out);
}

// round 2
// speedup vs baseline: 1.8925x; 1.8925x over previous
#include <cuda_runtime.h>
#include <cuda_bf16.h>
#include <cstdint>

#define L 256
#define D 128
#define H 4
#define DH 32
#define SCALING 0.17677669529663687f

typedef unsigned long long u64;

// ---- packed f32x2 helpers (sm_103a FFMA2 path; ptxas never auto-fuses) ----
__device__ __forceinline__ u64 pk2(float x, float y) {
    u64 r; asm("mov.b64 %0,{%1,%2};" : "=l"(r) : "f"(x), "f"(y)); return r;
}
__device__ __forceinline__ void upk2(u64 a, float& x, float& y) {
    asm("mov.b64 {%0,%1},%2;" : "=f"(x), "=f"(y) : "l"(a));
}
__device__ __forceinline__ u64 fma2(u64 a, u64 b, u64 c) {
    u64 d; asm("fma.rn.f32x2 %0,%1,%2,%3;" : "=l"(d) : "l"(a), "l"(b), "l"(c)); return d;
}
__device__ __forceinline__ u64 mul2(u64 a, u64 b) {
    u64 d; asm("mul.rn.f32x2 %0,%1,%2;" : "=l"(d) : "l"(a), "l"(b)); return d;
}

// ---- scratch (static device globals; no runtime allocation) ----
__device__ __align__(16) float g_q[L * L * D];
__device__ __align__(16) float g_k[L * L * D];
__device__ __align__(16) float g_v[L * L * D];
__device__ __align__(16) float g_gate[L * L * D];
__device__ __align__(16) float g_att[L * L * D];
__device__ __align__(16) float g_biasT[H * L * L];   // [h][k][j]

#define RB 64           // rows per block in proj/epi
#define XP (D + 4)      // padded smem row stride (528B = 33*16B: f4-aligned, bank-skewed)

// 4-row x 8-col register-blocked GEMV using f32x2.
// x0..x3: smem rows (broadcast reads). W row-major [D][D]. acc[4][4] f32x2 pairs.
__device__ __forceinline__ void gemv2(const float* __restrict__ x0,
                                      const float* __restrict__ x1,
                                      const float* __restrict__ x2,
                                      const float* __restrict__ x3,
                                      const float* __restrict__ W,
                                      int c0, u64 acc[4][4])
{
#pragma unroll
    for (int i = 0; i < 4; ++i)
#pragma unroll
        for (int p = 0; p < 4; ++p) acc[i][p] = 0ull;

#pragma unroll 4
    for (int d = 0; d < D; ++d) {
        u64 xx0 = pk2(x0[d], x0[d]);
        u64 xx1 = pk2(x1[d], x1[d]);
        u64 xx2 = pk2(x2[d], x2[d]);
        u64 xx3 = pk2(x3[d], x3[d]);
        const ulonglong2* wp = reinterpret_cast<const ulonglong2*>(W + d * D + c0);
        ulonglong2 wa = wp[0];           // cols c0..c0+3 as 2 f32x2
        ulonglong2 wb = wp[1];           // cols c0+4..c0+7
        acc[0][0] = fma2(xx0, wa.x, acc[0][0]); acc[0][1] = fma2(xx0, wa.y, acc[0][1]);
        acc[0][2] = fma2(xx0, wb.x, acc[0][2]); acc[0][3] = fma2(xx0, wb.y, acc[0][3]);
        acc[1][0] = fma2(xx1, wa.x, acc[1][0]); acc[1][1] = fma2(xx1, wa.y, acc[1][1]);
        acc[1][2] = fma2(xx1, wb.x, acc[1][2]); acc[1][3] = fma2(xx1, wb.y, acc[1][3]);
        acc[2][0] = fma2(xx2, wa.x, acc[2][0]); acc[2][1] = fma2(xx2, wa.y, acc[2][1]);
        acc[2][2] = fma2(xx2, wb.x, acc[2][2]); acc[2][3] = fma2(xx2, wb.y, acc[2][3]);
        acc[3][0] = fma2(xx3, wa.x, acc[3][0]); acc[3][1] = fma2(xx3, wa.y, acc[3][1]);
        acc[3][2] = fma2(xx3, wb.x, acc[3][2]); acc[3][3] = fma2(xx3, wb.y, acc[3][3]);
    }
}

// Kernel A: LayerNorm + Q/K/V/gate projections + attention bias (transposed store).
// 256 threads handle RB=64 pair-positions; thread = 4 rows x 8 cols.
__global__ void __launch_bounds__(256) proj_kernel(
    const float* __restrict__ pair,
    const float* __restrict__ gamma, const float* __restrict__ beta,
    const float* __restrict__ Wq, const float* __restrict__ Wk,
    const float* __restrict__ Wv, const float* __restrict__ Wb,
    const float* __restrict__ Wg, const float* __restrict__ bg)
{
    __shared__ float xs[RB][XP];
    const int t = threadIdx.x;
    const int warp = t >> 5, lane = t & 31;
    const int p0 = blockIdx.x * RB;

    // ---- LayerNorm: warp w handles rows w*8 .. w*8+7 ----
    float4 gv = reinterpret_cast<const float4*>(gamma)[lane];
    float4 bv = reinterpret_cast<const float4*>(beta)[lane];
#pragma unroll
    for (int rr = 0; rr < 8; ++rr) {
        int r = warp * 8 + rr;
        float4 x = reinterpret_cast<const float4*>(pair + (size_t)(p0 + r) * D)[lane];
        float s  = x.x + x.y + x.z + x.w;
        float s2 = x.x * x.x + x.y * x.y + x.z * x.z + x.w * x.w;
#pragma unroll
        for (int o = 16; o > 0; o >>= 1) {
            s  += __shfl_xor_sync(0xffffffffu, s,  o);
            s2 += __shfl_xor_sync(0xffffffffu, s2, o);
        }
        float mu  = s * (1.0f / 128.0f);
        float var = s2 * (1.0f / 128.0f) - mu * mu;
        float rs  = rsqrtf(var + 1e-5f);
        float4 xn;
        xn.x = (x.x - mu) * rs * gv.x + bv.x;
        xn.y = (x.y - mu) * rs * gv.y + bv.y;
        xn.z = (x.z - mu) * rs * gv.z + bv.z;
        xn.w = (x.w - mu) * rs * gv.w + bv.w;
        reinterpret_cast<float4*>(&xs[r][0])[lane] = xn;
    }
    __syncthreads();

    // ---- projections: thread -> (rows rg*4..+3, 8 columns at c0) ----
    const int rg = t >> 4;
    const int c0 = (t & 15) * 8;
    const int r0 = rg * 4;
    const float* x0 = &xs[r0 + 0][0];
    const float* x1 = &xs[r0 + 1][0];
    const float* x2 = &xs[r0 + 2][0];
    const float* x3 = &xs[r0 + 3][0];

    u64 acc[4][4];

    {   // Q (scaled)
        gemv2(x0, x1, x2, x3, Wq, c0, acc);
        u64 sc = pk2(SCALING, SCALING);
#pragma unroll
        for (int i = 0; i < 4; ++i) {
            size_t prow = (size_t)(p0 + r0 + i) * D + c0;
            ulonglong2 s0 = {mul2(acc[i][0], sc), mul2(acc[i][1], sc)};
            ulonglong2 s1 = {mul2(acc[i][2], sc), mul2(acc[i][3], sc)};
            reinterpret_cast<ulonglong2*>(g_q + prow)[0] = s0;
            reinterpret_cast<ulonglong2*>(g_q + prow + 4)[0] = s1;
        }
    }
    {   // K
        gemv2(x0, x1, x2, x3, Wk, c0, acc);
#pragma unroll
        for (int i = 0; i < 4; ++i) {
            size_t prow = (size_t)(p0 + r0 + i) * D + c0;
            reinterpret_cast<ulonglong2*>(g_k + prow)[0]     = ulonglong2{acc[i][0], acc[i][1]};
            reinterpret_cast<ulonglong2*>(g_k + prow + 4)[0] = ulonglong2{acc[i][2], acc[i][3]};
        }
    }
    {   // V
        gemv2(x0, x1, x2, x3, Wv, c0, acc);
#pragma unroll
        for (int i = 0; i < 4; ++i) {
            size_t prow = (size_t)(p0 + r0 + i) * D + c0;
            reinterpret_cast<ulonglong2*>(g_v + prow)[0]     = ulonglong2{acc[i][0], acc[i][1]};
            reinterpret_cast<ulonglong2*>(g_v + prow + 4)[0] = ulonglong2{acc[i][2], acc[i][3]};
        }
    }
    {   // gate = sigmoid(x@Wg + bg)
        gemv2(x0, x1, x2, x3, Wg, c0, acc);
        float bgv[8];
#pragma unroll
        for (int c = 0; c < 8; ++c) bgv[c] = bg[c0 + c];
#pragma unroll
        for (int i = 0; i < 4; ++i) {
            float f[8];
            upk2(acc[i][0], f[0], f[1]); upk2(acc[i][1], f[2], f[3]);
            upk2(acc[i][2], f[4], f[5]); upk2(acc[i][3], f[6], f[7]);
#pragma unroll
            for (int c = 0; c < 8; ++c) {
                float z = f[c] + bgv[c];
                f[c] = 1.0f / (1.0f + __expf(-z));
            }
            size_t prow = (size_t)(p0 + r0 + i) * D + c0;
            *reinterpret_cast<float4*>(g_gate + prow)     = make_float4(f[0], f[1], f[2], f[3]);
            *reinterpret_cast<float4*>(g_gate + prow + 4) = make_float4(f[4], f[5], f[6], f[7]);
        }
    }

    // ---- bias = x @ Wb, stored transposed as [h][k][j] ----
    {
        int rb = t >> 2;      // row 0..63
        int hb = t & 3;       // head
        float accb = 0.0f;
#pragma unroll 4
        for (int d = 0; d < D; ++d) accb += xs[rb][d] * Wb[d * H + hb];
        int p = p0 + rb;
        int jj = p >> 8;
        int kk = p & 255;
        g_biasT[((size_t)hb * L + kk) * L + jj] = accb;
    }
}

// Kernel B: attention for one (row i, head h) per block; thread = query index j.
// K/V in smem as f32x2 pairs; FFMA2 inner loop; bias double-buffered per 8-k chunk.
__global__ void __launch_bounds__(256) attn_kernel()
{
    extern __shared__ float sm[];
    float* sK = sm;            // [256][32]
    float* sV = sm + L * DH;   // [256][32]

    const int i = blockIdx.x;
    const int h = blockIdx.y;
    const int t = threadIdx.x;          // j

    const size_t base = (size_t)i * L * D + (size_t)h * DH;
    for (int idx = t; idx < L * DH / 4; idx += 256) {
        int k  = idx >> 3;
        int u  = idx & 7;
        reinterpret_cast<float4*>(sK + k * DH)[u] =
            reinterpret_cast<const float4*>(g_k + base + (size_t)k * D)[u];
        reinterpret_cast<float4*>(sV + k * DH)[u] =
            reinterpret_cast<const float4*>(g_v + base + (size_t)k * D)[u];
    }
    __syncthreads();

    // q[j] as 16 f32x2
    u64 q2[16];
    const size_t qbase = base + (size_t)t * D;
#pragma unroll
    for (int u = 0; u < 8; ++u) {
        ulonglong2 v = reinterpret_cast<const ulonglong2*>(g_q + qbase)[u];
        q2[2 * u] = v.x; q2[2 * u + 1] = v.y;
    }

    const float* biasp = g_biasT + (size_t)h * L * L + t;   // + k*L per step

    u64 out2[16];
#pragma unroll
    for (int u = 0; u < 16; ++u) out2[u] = 0ull;
    float ssum = 0.0f;

    float bc[8], bn[8];
#pragma unroll
    for (int u = 0; u < 8; ++u) bc[u] = biasp[(size_t)u * L];

    for (int k0 = 0; k0 < L; k0 += 8) {
        if (k0 + 8 < L) {
#pragma unroll
            for (int u = 0; u < 8; ++u) bn[u] = biasp[(size_t)(k0 + 8 + u) * L];
        }
#pragma unroll
        for (int kk = 0; kk < 8; ++kk) {
            const int k = k0 + kk;
            const ulonglong2* kr = reinterpret_cast<const ulonglong2*>(sK + k * DH);
            u64 s2a = 0ull, s2b = 0ull;
#pragma unroll
            for (int u = 0; u < 8; ++u) {
                ulonglong2 kv = kr[u];
                s2a = fma2(q2[2 * u],     kv.x, s2a);
                s2b = fma2(q2[2 * u + 1], kv.y, s2b);
            }
            float sa0, sa1, sb0, sb1;
            upk2(s2a, sa0, sa1);
            upk2(s2b, sb0, sb1);
            float s = (sa0 + sa1) + (sb0 + sb1) + bc[kk];
            float pw = __expf(s);
            ssum += pw;
            u64 pw2 = pk2(pw, pw);
            const ulonglong2* vr = reinterpret_cast<const ulonglong2*>(sV + k * DH);
#pragma unroll
            for (int u = 0; u < 8; ++u) {
                ulonglong2 vv = vr[u];
                out2[2 * u]     = fma2(pw2, vv.x, out2[2 * u]);
                out2[2 * u + 1] = fma2(pw2, vv.y, out2[2 * u + 1]);
            }
        }
#pragma unroll
        for (int u = 0; u < 8; ++u) bc[u] = bn[u];
    }

    float inv = 1.0f / ssum;
    u64 inv2 = pk2(inv, inv);
    float* op = g_att + qbase;
#pragma unroll
    for (int u = 0; u < 8; ++u) {
        ulonglong2 o = {mul2(out2[2 * u], inv2), mul2(out2[2 * u + 1], inv2)};
        reinterpret_cast<ulonglong2*>(op)[u] = o;
    }
}

// Kernel C: out = (gate * att) @ Wo + bo  (register-blocked like proj)
__global__ void __launch_bounds__(256) epi_kernel(
    const float* __restrict__ Wo, const float* __restrict__ bo,
    float* __restrict__ out)
{
    __shared__ float ys[RB][XP];
    const int t = threadIdx.x;
    const int p0 = blockIdx.x * RB;

#pragma unroll
    for (int u = 0; u < 8; ++u) {
        int idx = u * 256 + t;           // float4 units over 64x128
        int r = idx >> 5, q = idx & 31;
        size_t off = (size_t)(p0 + r) * D + q * 4;
        float4 g = *reinterpret_cast<const float4*>(g_gate + off);
        float4 a = *reinterpret_cast<const float4*>(g_att + off);
        float4 y = {g.x * a.x, g.y * a.y, g.z * a.z, g.w * a.w};
        reinterpret_cast<float4*>(&ys[r][0])[q] = y;
    }
    __syncthreads();

    const int rg = t >> 4;
    const int c0 = (t & 15) * 8;
    const int r0 = rg * 4;

    u64 acc[4][4];
    gemv2(&ys[r0][0], &ys[r0 + 1][0], &ys[r0 + 2][0], &ys[r0 + 3][0], Wo, c0, acc);

    float bov[8];
#pragma unroll
    for (int c = 0; c < 8; ++c) bov[c] = bo[c0 + c];

#pragma unroll
    for (int i = 0; i < 4; ++i) {
        float f[8];
        upk2(acc[i][0], f[0], f[1]); upk2(acc[i][1], f[2], f[3]);
        upk2(acc[i][2], f[4], f[5]); upk2(acc[i][3], f[6], f[7]);
        size_t prow = (size_t)(p0 + r0 + i) * D + c0;
        *reinterpret_cast<float4*>(out + prow) =
            make_float4(f[0] + bov[0], f[1] + bov[1], f[2] + bov[2], f[3] + bov[3]);
        *reinterpret_cast<float4*>(out + prow + 4) =
            make_float4(f[4] + bov[4], f[5] + bov[5], f[6] + bov[6], f[7] + bov[7]);
    }
}

extern "C" void kernel_launch(void* const* d_in, const int* in_sizes, int n_in,
                              void* d_out, int out_size)
{
    const float* pair  = (const float*)d_in[0];
    const float* gamma = (const float*)d_in[1];
    const float* beta  = (const float*)d_in[2];
    const float* Wq    = (const float*)d_in[3];
    const float* Wk    = (const float*)d_in[4];
    const float* Wv    = (const float*)d_in[5];
    const float* Wb    = (const float*)d_in[6];
    const float* Wg    = (const float*)d_in[7];
    const float* bg    = (const float*)d_in[8];
    const float* Wo    = (const float*)d_in[9];
    const float* bo    = (const float*)d_in[10];
    float* out = (float*)d_out;

    cudaFuncSetAttribute(attn_kernel, cudaFuncAttributeMaxDynamicSharedMemorySize,
                         2 * L * DH * (int)sizeof(float));

    proj_kernel<<<(L * L) / RB, 256>>>(pair, gamma, beta, Wq, Wk, Wv, Wb, Wg, bg);
    attn_kernel<<<dim3(L, H), 256, 2 * L * DH * sizeof(float)>>>();
    epi_kernel<<<(L * L) / RB, 256>>>(Wo, bo, out);
}

// round 4
// speedup vs baseline: 2.6467x; 1.3985x over previous
#include <cuda_runtime.h>
#include <cuda_bf16.h>
#include <mma.h>
#include <cstdint>

using namespace nvcuda;

#define L 256
#define D 128
#define H 4
#define DH 32
#define SCALING 0.17677669529663687f

typedef unsigned long long u64;

__device__ __forceinline__ u64 pk2(float x, float y) {
    u64 r; asm("mov.b64 %0,{%1,%2};" : "=l"(r) : "f"(x), "f"(y)); return r;
}
__device__ __forceinline__ void upk2(u64 a, float& x, float& y) {
    asm("mov.b64 {%0,%1},%2;" : "=f"(x), "=f"(y) : "l"(a));
}
__device__ __forceinline__ u64 fma2(u64 a, u64 b, u64 c) {
    u64 d; asm("fma.rn.f32x2 %0,%1,%2,%3;" : "=l"(d) : "l"(a), "l"(b), "l"(c)); return d;
}
__device__ __forceinline__ u64 mul2(u64 a, u64 b) {
    u64 d; asm("mul.rn.f32x2 %0,%1,%2;" : "=l"(d) : "l"(a), "l"(b)); return d;
}

__device__ __align__(16) float g_q[L * L * D];
__device__ __align__(16) float g_k[L * L * D];
__device__ __align__(16) float g_v[L * L * D];
__device__ __align__(16) float g_gate[L * L * D];
__device__ __align__(16) float g_att[L * L * D];
__device__ __align__(16) float g_biasT[H * L * L];
__device__ __align__(16) __nv_bfloat16 g_B_hi[128 * 512];
__device__ __align__(16) __nv_bfloat16 g_B_lo[128 * 512];

__device__ __forceinline__ __nv_bfloat16 bhi(float x) { return __float2bfloat16_rn(x); }
__device__ __forceinline__ __nv_bfloat16 blo(float x, __nv_bfloat16 h) {
    return __float2bfloat16_rn(x - __bfloat162float(h));
}

__global__ void __launch_bounds__(256) prep_kernel(
    const float* __restrict__ Wq, const float* __restrict__ Wk,
    const float* __restrict__ Wv, const float* __restrict__ Wg)
{
    int idx = blockIdx.x * 256 + threadIdx.x;
    int k = idx >> 9;
    int n = idx & 511;
    const float* W = (n < 128) ? Wq : (n < 256) ? Wk : (n < 384) ? Wv : Wg;
    float w = W[k * 128 + (n & 127)];
    __nv_bfloat16 h = bhi(w);
    g_B_hi[idx] = h;
    g_B_lo[idx] = blo(w, h);
}

#define LDA 136
#define LDB 136
#define A_HI_OFF 0
#define A_LO_OFF (128 * LDA * 2)
#define B_HI_OFF (2 * 128 * LDA * 2)
#define B_LO_OFF (B_HI_OFF + 128 * LDB * 2)
#define PROJ_SMEM (B_LO_OFF + 128 * LDB * 2)
#define STAGE_OFF B_HI_OFF

__global__ void __launch_bounds__(256) proj_wmma_kernel(
    const float* __restrict__ pair,
    const float* __restrict__ gamma, const float* __restrict__ beta,
    const float* __restrict__ Wb, const float* __restrict__ bg)
{
    extern __shared__ char smem[];
    __nv_bfloat16* sAhi = reinterpret_cast<__nv_bfloat16*>(smem + A_HI_OFF);
    __nv_bfloat16* sAlo = reinterpret_cast<__nv_bfloat16*>(smem + A_LO_OFF);
    __nv_bfloat16* sBhi = reinterpret_cast<__nv_bfloat16*>(smem + B_HI_OFF);
    __nv_bfloat16* sBlo = reinterpret_cast<__nv_bfloat16*>(smem + B_LO_OFF);
    float* stage = reinterpret_cast<float*>(smem + STAGE_OFF);

    const int t = threadIdx.x;
    const int wid = t >> 5, lane = t & 31;
    const int row0 = blockIdx.x * 128;

    float4 gv = reinterpret_cast<const float4*>(gamma)[lane];
    float4 bv = reinterpret_cast<const float4*>(beta)[lane];
    float4 wbr[4];
#pragma unroll
    for (int i = 0; i < 4; ++i)
        wbr[i] = *reinterpret_cast<const float4*>(Wb + (lane * 4 + i) * 4);

#pragma unroll 2
    for (int rr = 0; rr < 16; ++rr) {
        int r = wid * 16 + rr;
        float4 x = reinterpret_cast<const float4*>(pair + (size_t)(row0 + r) * D)[lane];
        float s  = x.x + x.y + x.z + x.w;
        float s2 = x.x * x.x + x.y * x.y + x.z * x.z + x.w * x.w;
#pragma unroll
        for (int o = 16; o > 0; o >>= 1) {
            s  += __shfl_xor_sync(0xffffffffu, s,  o);
            s2 += __shfl_xor_sync(0xffffffffu, s2, o);
        }
        float mu  = s * (1.0f / 128.0f);
        float var = s2 * (1.0f / 128.0f) - mu * mu;
        float rs  = rsqrtf(var + 1e-5f);
        float4 xn;
        xn.x = (x.x - mu) * rs * gv.x + bv.x;
        xn.y = (x.y - mu) * rs * gv.y + bv.y;
        xn.z = (x.z - mu) * rs * gv.z + bv.z;
        xn.w = (x.w - mu) * rs * gv.w + bv.w;

        __nv_bfloat16 h0 = bhi(xn.x), h1 = bhi(xn.y), h2 = bhi(xn.z), h3 = bhi(xn.w);
        __nv_bfloat162 hA = {h0, h1}, hB = {h2, h3};
        __nv_bfloat162 lA = {blo(xn.x, h0), blo(xn.y, h1)};
        __nv_bfloat162 lB = {blo(xn.z, h2), blo(xn.w, h3)};
        size_t aoff = (size_t)r * LDA + lane * 4;
        *reinterpret_cast<__nv_bfloat162*>(sAhi + aoff)     = hA;
        *reinterpret_cast<__nv_bfloat162*>(sAhi + aoff + 2) = hB;
        *reinterpret_cast<__nv_bfloat162*>(sAlo + aoff)     = lA;
        *reinterpret_cast<__nv_bfloat162*>(sAlo + aoff + 2) = lB;

        float4 bacc;
        bacc.x = xn.x * wbr[0].x + xn.y * wbr[1].x + xn.z * wbr[2].x + xn.w * wbr[3].x;
        bacc.y = xn.x * wbr[0].y + xn.y * wbr[1].y + xn.z * wbr[2].y + xn.w * wbr[3].y;
        bacc.z = xn.x * wbr[0].z + xn.y * wbr[1].z + xn.z * wbr[2].z + xn.w * wbr[3].z;
        bacc.w = xn.x * wbr[0].w + xn.y * wbr[1].w + xn.z * wbr[2].w + xn.w * wbr[3].w;
#pragma unroll
        for (int o = 16; o > 0; o >>= 1) {
            bacc.x += __shfl_xor_sync(0xffffffffu, bacc.x, o);
            bacc.y += __shfl_xor_sync(0xffffffffu, bacc.y, o);
            bacc.z += __shfl_xor_sync(0xffffffffu, bacc.z, o);
            bacc.w += __shfl_xor_sync(0xffffffffu, bacc.w, o);
        }
        if (lane == 0) {
            int p = row0 + r, jj = p >> 8, kk = p & 255;
            g_biasT[((size_t)0 * L + kk) * L + jj] = bacc.x;
            g_biasT[((size_t)1 * L + kk) * L + jj] = bacc.y;
            g_biasT[((size_t)2 * L + kk) * L + jj] = bacc.z;
            g_biasT[((size_t)3 * L + kk) * L + jj] = bacc.w;
        }
    }
    __syncthreads();

    const int wm = (wid & 3) * 32;
    const int wn = (wid >> 2) * 64;

    for (int c = 0; c < 4; ++c) {
#pragma unroll
        for (int it = 0; it < 8; ++it) {
            int idx = it * 256 + t;
            int k = idx >> 4, u = idx & 15;
            size_t src = (size_t)k * 512 + c * 128 + u * 8;
            size_t dst = (size_t)k * LDB + u * 8;
            *reinterpret_cast<uint4*>(sBhi + dst) = *reinterpret_cast<const uint4*>(g_B_hi + src);
            *reinterpret_cast<uint4*>(sBlo + dst) = *reinterpret_cast<const uint4*>(g_B_lo + src);
        }
        __syncthreads();

        wmma::fragment<wmma::accumulator, 16, 16, 16, float> acc[2][4];
#pragma unroll
        for (int i = 0; i < 2; ++i)
#pragma unroll
            for (int j = 0; j < 4; ++j) wmma::fill_fragment(acc[i][j], 0.0f);

#pragma unroll
        for (int pass = 0; pass < 3; ++pass) {
            const __nv_bfloat16* Ap = (pass == 2) ? sAlo : sAhi;
            const __nv_bfloat16* Bp = (pass == 1) ? sBlo : sBhi;
#pragma unroll
            for (int k8 = 0; k8 < 8; ++k8) {
                wmma::fragment<wmma::matrix_a, 16, 16, 16, __nv_bfloat16, wmma::row_major> af[2];
                wmma::load_matrix_sync(af[0], Ap + (size_t)(wm +  0) * LDA + k8 * 16, LDA);
                wmma::load_matrix_sync(af[1], Ap + (size_t)(wm + 16) * LDA + k8 * 16, LDA);
                wmma::fragment<wmma::matrix_b, 16, 16, 16, __nv_bfloat16, wmma::row_major> bf;
#pragma unroll
                for (int j = 0; j < 4; ++j) {
                    wmma::load_matrix_sync(bf, Bp + (size_t)(k8 * 16) * LDB + wn + j * 16, LDB);
                    wmma::mma_sync(acc[0][j], af[0], bf, acc[0][j]);
                    wmma::mma_sync(acc[1][j], af[1], bf, acc[1][j]);
                }
            }
        }

        if (c < 3) {
            float* dst = (c == 0) ? g_q : (c == 1) ? g_k : g_v;
            if (c == 0) {
#pragma unroll
                for (int i = 0; i < 2; ++i)
#pragma unroll
                    for (int j = 0; j < 4; ++j)
#pragma unroll
                        for (int e = 0; e < acc[i][j].num_elements; ++e)
                            acc[i][j].x[e] *= SCALING;
            }
#pragma unroll
            for (int i = 0; i < 2; ++i)
#pragma unroll
                for (int j = 0; j < 4; ++j)
                    wmma::store_matrix_sync(
                        dst + (size_t)(row0 + wm + i * 16) * D + wn + j * 16,
                        acc[i][j], D, wmma::mem_row_major);
            __syncthreads();
        } else {
            __syncthreads();
#pragma unroll
            for (int i = 0; i < 2; ++i)
#pragma unroll
                for (int j = 0; j < 4; ++j)
                    wmma::store_matrix_sync(
                        stage + (size_t)(wm + i * 16) * 128 + wn + j * 16,
                        acc[i][j], 128, wmma::mem_row_major);
            __syncthreads();
#pragma unroll
            for (int it = 0; it < 16; ++it) {
                int idx = it * 256 + t;
                int r = idx >> 5, q = idx & 31;
                float4 v = *reinterpret_cast<const float4*>(stage + (size_t)r * 128 + q * 4);
                float4 bgv = *reinterpret_cast<const float4*>(bg + q * 4);
                float4 o;
                o.x = 1.0f / (1.0f + __expf(-(v.x + bgv.x)));
                o.y = 1.0f / (1.0f + __expf(-(v.y + bgv.y)));
                o.z = 1.0f / (1.0f + __expf(-(v.z + bgv.z)));
                o.w = 1.0f / (1.0f + __expf(-(v.w + bgv.w)));
                *reinterpret_cast<float4*>(g_gate + (size_t)(row0 + r) * D + q * 4) = o;
            }
        }
    }
}

__global__ void __launch_bounds__(256) attn_kernel()
{
    extern __shared__ float sm[];
    float* sK = sm;
    float* sV = sm + L * DH;

    const int i = blockIdx.x;
    const int h = blockIdx.y;
    const int t = threadIdx.x;

    const size_t base = (size_t)i * L * D + (size_t)h * DH;
    for (int idx = t; idx < L * DH / 4; idx += 256) {
        int k  = idx >> 3;
        int u  = idx & 7;
        reinterpret_cast<float4*>(sK + k * DH)[u] =
            reinterpret_cast<const float4*>(g_k + base + (size_t)k * D)[u];
        reinterpret_cast<float4*>(sV + k * DH)[u] =
            reinterpret_cast<const float4*>(g_v + base + (size_t)k * D)[u];
    }
    __syncthreads();

    u64 q2[16];
    const size_t qbase = base + (size_t)t * D;
#pragma unroll
    for (int u = 0; u < 8; ++u) {
        ulonglong2 v = reinterpret_cast<const ulonglong2*>(g_q + qbase)[u];
        q2[2 * u] = v.x; q2[2 * u + 1] = v.y;
    }

    const float* biasp = g_biasT + (size_t)h * L * L + t;

    u64 out2[16];
#pragma unroll
    for (int u = 0; u < 16; ++u) out2[u] = 0ull;
    float ssum = 0.0f;

    float bc[8], bn[8];
#pragma unroll
    for (int u = 0; u < 8; ++u) bc[u] = biasp[(size_t)u * L];

    for (int k0 = 0; k0 < L; k0 += 8) {
        if (k0 + 8 < L) {
#pragma unroll
            for (int u = 0; u < 8; ++u) bn[u] = biasp[(size_t)(k0 + 8 + u) * L];
        }
#pragma unroll
        for (int kk = 0; kk < 8; ++kk) {
            const int k = k0 + kk;
            const ulonglong2* kr = reinterpret_cast<const ulonglong2*>(sK + k * DH);
            u64 s2a = 0ull, s2b = 0ull;
#pragma unroll
            for (int u = 0; u < 8; ++u) {
                ulonglong2 kv = kr[u];
                s2a = fma2(q2[2 * u],     kv.x, s2a);
                s2b = fma2(q2[2 * u + 1], kv.y, s2b);
            }
            float sa0, sa1, sb0, sb1;
            upk2(s2a, sa0, sa1);
            upk2(s2b, sb0, sb1);
            float s = (sa0 + sa1) + (sb0 + sb1) + bc[kk];
            float pw = __expf(s);
            ssum += pw;
            u64 pw2 = pk2(pw, pw);
            const ulonglong2* vr = reinterpret_cast<const ulonglong2*>(sV + k * DH);
#pragma unroll
            for (int u = 0; u < 8; ++u) {
                ulonglong2 vv = vr[u];
                out2[2 * u]     = fma2(pw2, vv.x, out2[2 * u]);
                out2[2 * u + 1] = fma2(pw2, vv.y, out2[2 * u + 1]);
            }
        }
#pragma unroll
        for (int u = 0; u < 8; ++u) bc[u] = bn[u];
    }

    float inv = 1.0f / ssum;
    u64 inv2 = pk2(inv, inv);
    float* op = g_att + qbase;
#pragma unroll
    for (int u = 0; u < 8; ++u) {
        ulonglong2 o = {mul2(out2[2 * u], inv2), mul2(out2[2 * u + 1], inv2)};
        reinterpret_cast<ulonglong2*>(op)[u] = o;
    }
}

#define RB 64
#define XP (D + 4)

__device__ __forceinline__ void gemv2(const float* __restrict__ x0,
                                      const float* __restrict__ x1,
                                      const float* __restrict__ x2,
                                      const float* __restrict__ x3,
                                      const float* __restrict__ W,
                                      int c0, u64 acc[4][4])
{
#pragma unroll
    for (int i = 0; i < 4; ++i)
#pragma unroll
        for (int p = 0; p < 4; ++p) acc[i][p] = 0ull;

#pragma unroll 4
    for (int d = 0; d < D; ++d) {
        u64 xx0 = pk2(x0[d], x0[d]);
        u64 xx1 = pk2(x1[d], x1[d]);
        u64 xx2 = pk2(x2[d], x2[d]);
        u64 xx3 = pk2(x3[d], x3[d]);
        const ulonglong2* wp = reinterpret_cast<const ulonglong2*>(W + d * D + c0);
        ulonglong2 wa = wp[0];
        ulonglong2 wb = wp[1];
        acc[0][0] = fma2(xx0, wa.x, acc[0][0]); acc[0][1] = fma2(xx0, wa.y, acc[0][1]);
        acc[0][2] = fma2(xx0, wb.x, acc[0][2]); acc[0][3] = fma2(xx0, wb.y, acc[0][3]);
        acc[1][0] = fma2(xx1, wa.x, acc[1][0]); acc[1][1] = fma2(xx1, wa.y, acc[1][1]);
        acc[1][2] = fma2(xx1, wb.x, acc[1][2]); acc[1][3] = fma2(xx1, wb.y, acc[1][3]);
        acc[2][0] = fma2(xx2, wa.x, acc[2][0]); acc[2][1] = fma2(xx2, wa.y, acc[2][1]);
        acc[2][2] = fma2(xx2, wb.x, acc[2][2]); acc[2][3] = fma2(xx2, wb.y, acc[2][3]);
        acc[3][0] = fma2(xx3, wa.x, acc[3][0]); acc[3][1] = fma2(xx3, wa.y, acc[3][1]);
        acc[3][2] = fma2(xx3, wb.x, acc[3][2]); acc[3][3] = fma2(xx3, wb.y, acc[3][3]);
    }
}

__global__ void __launch_bounds__(256) epi_kernel(
    const float* __restrict__ Wo, const float* __restrict__ bo,
    float* __restrict__ out)
{
    __shared__ float ys[RB][XP];
    const int t = threadIdx.x;
    const int p0 = blockIdx.x * RB;

#pragma unroll
    for (int u = 0; u < 8; ++u) {
        int idx = u * 256 + t;
        int r = idx >> 5, q = idx & 31;
        size_t off = (size_t)(p0 + r) * D + q * 4;
        float4 g = *reinterpret_cast<const float4*>(g_gate + off);
        float4 a = *reinterpret_cast<const float4*>(g_att + off);
        float4 y = {g.x * a.x, g.y * a.y, g.z * a.z, g.w * a.w};
        reinterpret_cast<float4*>(&ys[r][0])[q] = y;
    }
    __syncthreads();

    const int rg = t >> 4;
    const int c0 = (t & 15) * 8;
    const int r0 = rg * 4;

    u64 acc[4][4];
    gemv2(&ys[r0][0], &ys[r0 + 1][0], &ys[r0 + 2][0], &ys[r0 + 3][0], Wo, c0, acc);

    float bov[8];
#pragma unroll
    for (int c = 0; c < 8; ++c) bov[c] = bo[c0 + c];

#pragma unroll
    for (int i = 0; i < 4; ++i) {
        float f[8];
        upk2(acc[i][0], f[0], f[1]); upk2(acc[i][1], f[2], f[3]);
        upk2(acc[i][2], f[4], f[5]); upk2(acc[i][3], f[6], f[7]);
        size_t prow = (size_t)(p0 + r0 + i) * D + c0;
        *reinterpret_cast<float4*>(out + prow) =
            make_float4(f[0] + bov[0], f[1] + bov[1], f[2] + bov[2], f[3] + bov[3]);
        *reinterpret_cast<float4*>(out + prow + 4) =
            make_float4(f[4] + bov[4], f[5] + bov[5], f[6] + bov[6], f[7] + bov[7]);
    }
}

extern "C" void kernel_launch(void* const* d_in, const int* in_sizes, int n_in,
                              void* d_out, int out_size)
{
    const float* pair  = (const float*)d_in[0];
    const float* gamma = (const float*)d_in[1];
    const float* beta  = (const float*)d_in[2];
    const float* Wq    = (const float*)d_in[3];
    const float* Wk    = (const float*)d_in[4];
    const float* Wv    = (const float*)d_in[5];
    const float* Wb    = (const float*)d_in[6];
    const float* Wg    = (const float*)d_in[7];
    const float* bg    = (const float*)d_in[8];
    const float* Wo    = (const float*)d_in[9];
    const float* bo    = (const float*)d_in[10];
    float* out = (float*)d_out;

    cudaFuncSetAttribute(proj_wmma_kernel, cudaFuncAttributeMaxDynamicSharedMemorySize,
                         PROJ_SMEM);
    cudaFuncSetAttribute(attn_kernel, cudaFuncAttributeMaxDynamicSharedMemorySize,
                         2 * L * DH * (int)sizeof(float));

    prep_kernel<<<256, 256>>>(Wq, Wk, Wv, Wg);
    proj_wmma_kernel<<<(L * L) / 128, 256, PROJ_SMEM>>>(pair, gamma, beta, Wb, bg);
    attn_kernel<<<dim3(L, H), 256, 2 * L * DH * sizeof(float)>>>();
    epi_kernel<<<(L * L) / RB, 256>>>(Wo, bo, out);
}

// round 6
// speedup vs baseline: 3.2635x; 1.2331x over previous
#include <cuda_runtime.h>
#include <cuda_bf16.h>
#include <mma.h>
#include <cstdint>

using namespace nvcuda;

#define L 256
#define D 128
#define H 4
#define DH 32
#define SCALING 0.17677669529663687f

// ---- scratch ----
__device__ __align__(16) float g_q[L * L * D];
__device__ __align__(16) float g_k[L * L * D];
__device__ __align__(16) float g_v[L * L * D];
__device__ __align__(16) float g_gate[L * L * D];
__device__ __align__(16) float g_att[L * L * D];
__device__ __align__(16) float g_biasH[H * L * L];           // [h][j][k]
__device__ __align__(16) __nv_bfloat16 g_B_hi[128 * 512];    // [k][n] (Wq|Wk|Wv|Wg)
__device__ __align__(16) __nv_bfloat16 g_B_lo[128 * 512];
__device__ __align__(16) __nv_bfloat16 g_Wo_hi[128 * 128];   // [k][n]
__device__ __align__(16) __nv_bfloat16 g_Wo_lo[128 * 128];

__device__ __forceinline__ __nv_bfloat16 bhi(float x) { return __float2bfloat16_rn(x); }
__device__ __forceinline__ __nv_bfloat16 blo(float x, __nv_bfloat16 h) {
    return __float2bfloat16_rn(x - __bfloat162float(h));
}

// ---- prep ----
__global__ void __launch_bounds__(256) prep_kernel(
    const float* __restrict__ Wq, const float* __restrict__ Wk,
    const float* __restrict__ Wv, const float* __restrict__ Wg,
    const float* __restrict__ Wo)
{
    if (blockIdx.x < 256) {
        int idx = blockIdx.x * 256 + threadIdx.x;
        int k = idx >> 9;
        int n = idx & 511;
        const float* W = (n < 128) ? Wq : (n < 256) ? Wk : (n < 384) ? Wv : Wg;
        float w = W[k * 128 + (n & 127)];
        __nv_bfloat16 h = bhi(w);
        g_B_hi[idx] = h;
        g_B_lo[idx] = blo(w, h);
    } else {
        int idx = (blockIdx.x - 256) * 256 + threadIdx.x;
        float w = Wo[idx];
        __nv_bfloat16 h = bhi(w);
        g_Wo_hi[idx] = h;
        g_Wo_lo[idx] = blo(w, h);
    }
}

// ============================= proj (unchanged, r4-verified) =============================
#define LDA 136
#define LDB 136
#define A_HI_OFF 0
#define A_LO_OFF (128 * LDA * 2)
#define B_HI_OFF (2 * 128 * LDA * 2)
#define B_LO_OFF (B_HI_OFF + 128 * LDB * 2)
#define PROJ_SMEM (B_LO_OFF + 128 * LDB * 2)
#define STAGE_OFF B_HI_OFF

__global__ void __launch_bounds__(256) proj_wmma_kernel(
    const float* __restrict__ pair,
    const float* __restrict__ gamma, const float* __restrict__ beta,
    const float* __restrict__ Wb, const float* __restrict__ bg)
{
    extern __shared__ char smem[];
    __nv_bfloat16* sAhi = reinterpret_cast<__nv_bfloat16*>(smem + A_HI_OFF);
    __nv_bfloat16* sAlo = reinterpret_cast<__nv_bfloat16*>(smem + A_LO_OFF);
    __nv_bfloat16* sBhi = reinterpret_cast<__nv_bfloat16*>(smem + B_HI_OFF);
    __nv_bfloat16* sBlo = reinterpret_cast<__nv_bfloat16*>(smem + B_LO_OFF);
    float* stage = reinterpret_cast<float*>(smem + STAGE_OFF);

    const int t = threadIdx.x;
    const int wid = t >> 5, lane = t & 31;
    const int row0 = blockIdx.x * 128;

    float4 gv = reinterpret_cast<const float4*>(gamma)[lane];
    float4 bv = reinterpret_cast<const float4*>(beta)[lane];
    float4 wbr[4];
#pragma unroll
    for (int i = 0; i < 4; ++i)
        wbr[i] = *reinterpret_cast<const float4*>(Wb + (lane * 4 + i) * 4);

#pragma unroll 2
    for (int rr = 0; rr < 16; ++rr) {
        int r = wid * 16 + rr;
        float4 x = reinterpret_cast<const float4*>(pair + (size_t)(row0 + r) * D)[lane];
        float s  = x.x + x.y + x.z + x.w;
        float s2 = x.x * x.x + x.y * x.y + x.z * x.z + x.w * x.w;
#pragma unroll
        for (int o = 16; o > 0; o >>= 1) {
            s  += __shfl_xor_sync(0xffffffffu, s,  o);
            s2 += __shfl_xor_sync(0xffffffffu, s2, o);
        }
        float mu  = s * (1.0f / 128.0f);
        float var = s2 * (1.0f / 128.0f) - mu * mu;
        float rs  = rsqrtf(var + 1e-5f);
        float4 xn;
        xn.x = (x.x - mu) * rs * gv.x + bv.x;
        xn.y = (x.y - mu) * rs * gv.y + bv.y;
        xn.z = (x.z - mu) * rs * gv.z + bv.z;
        xn.w = (x.w - mu) * rs * gv.w + bv.w;

        __nv_bfloat16 h0 = bhi(xn.x), h1 = bhi(xn.y), h2 = bhi(xn.z), h3 = bhi(xn.w);
        __nv_bfloat162 hA = {h0, h1}, hB = {h2, h3};
        __nv_bfloat162 lA = {blo(xn.x, h0), blo(xn.y, h1)};
        __nv_bfloat162 lB = {blo(xn.z, h2), blo(xn.w, h3)};
        size_t aoff = (size_t)r * LDA + lane * 4;
        *reinterpret_cast<__nv_bfloat162*>(sAhi + aoff)     = hA;
        *reinterpret_cast<__nv_bfloat162*>(sAhi + aoff + 2) = hB;
        *reinterpret_cast<__nv_bfloat162*>(sAlo + aoff)     = lA;
        *reinterpret_cast<__nv_bfloat162*>(sAlo + aoff + 2) = lB;

        float4 bacc;
        bacc.x = xn.x * wbr[0].x + xn.y * wbr[1].x + xn.z * wbr[2].x + xn.w * wbr[3].x;
        bacc.y = xn.x * wbr[0].y + xn.y * wbr[1].y + xn.z * wbr[2].y + xn.w * wbr[3].y;
        bacc.z = xn.x * wbr[0].z + xn.y * wbr[1].z + xn.z * wbr[2].z + xn.w * wbr[3].z;
        bacc.w = xn.x * wbr[0].w + xn.y * wbr[1].w + xn.z * wbr[2].w + xn.w * wbr[3].w;
#pragma unroll
        for (int o = 16; o > 0; o >>= 1) {
            bacc.x += __shfl_xor_sync(0xffffffffu, bacc.x, o);
            bacc.y += __shfl_xor_sync(0xffffffffu, bacc.y, o);
            bacc.z += __shfl_xor_sync(0xffffffffu, bacc.z, o);
            bacc.w += __shfl_xor_sync(0xffffffffu, bacc.w, o);
        }
        if (lane == 0) {
            int p = row0 + r;
            g_biasH[0 * 65536 + p] = bacc.x;
            g_biasH[1 * 65536 + p] = bacc.y;
            g_biasH[2 * 65536 + p] = bacc.z;
            g_biasH[3 * 65536 + p] = bacc.w;
        }
    }
    __syncthreads();

    const int wm = (wid & 3) * 32;
    const int wn = (wid >> 2) * 64;

    for (int c = 0; c < 4; ++c) {
#pragma unroll
        for (int it = 0; it < 8; ++it) {
            int idx = it * 256 + t;
            int k = idx >> 4, u = idx & 15;
            size_t src = (size_t)k * 512 + c * 128 + u * 8;
            size_t dst = (size_t)k * LDB + u * 8;
            *reinterpret_cast<uint4*>(sBhi + dst) = *reinterpret_cast<const uint4*>(g_B_hi + src);
            *reinterpret_cast<uint4*>(sBlo + dst) = *reinterpret_cast<const uint4*>(g_B_lo + src);
        }
        __syncthreads();

        wmma::fragment<wmma::accumulator, 16, 16, 16, float> acc[2][4];
#pragma unroll
        for (int i = 0; i < 2; ++i)
#pragma unroll
            for (int j = 0; j < 4; ++j) wmma::fill_fragment(acc[i][j], 0.0f);

#pragma unroll
        for (int pass = 0; pass < 3; ++pass) {
            const __nv_bfloat16* Ap = (pass == 2) ? sAlo : sAhi;
            const __nv_bfloat16* Bp = (pass == 1) ? sBlo : sBhi;
#pragma unroll
            for (int k8 = 0; k8 < 8; ++k8) {
                wmma::fragment<wmma::matrix_a, 16, 16, 16, __nv_bfloat16, wmma::row_major> af[2];
                wmma::load_matrix_sync(af[0], Ap + (size_t)(wm +  0) * LDA + k8 * 16, LDA);
                wmma::load_matrix_sync(af[1], Ap + (size_t)(wm + 16) * LDA + k8 * 16, LDA);
                wmma::fragment<wmma::matrix_b, 16, 16, 16, __nv_bfloat16, wmma::row_major> bf;
#pragma unroll
                for (int j = 0; j < 4; ++j) {
                    wmma::load_matrix_sync(bf, Bp + (size_t)(k8 * 16) * LDB + wn + j * 16, LDB);
                    wmma::mma_sync(acc[0][j], af[0], bf, acc[0][j]);
                    wmma::mma_sync(acc[1][j], af[1], bf, acc[1][j]);
                }
            }
        }

        if (c < 3) {
            float* dst = (c == 0) ? g_q : (c == 1) ? g_k : g_v;
            if (c == 0) {
#pragma unroll
                for (int i = 0; i < 2; ++i)
#pragma unroll
                    for (int j = 0; j < 4; ++j)
#pragma unroll
                        for (int e = 0; e < acc[i][j].num_elements; ++e)
                            acc[i][j].x[e] *= SCALING;
            }
#pragma unroll
            for (int i = 0; i < 2; ++i)
#pragma unroll
                for (int j = 0; j < 4; ++j)
                    wmma::store_matrix_sync(
                        dst + (size_t)(row0 + wm + i * 16) * D + wn + j * 16,
                        acc[i][j], D, wmma::mem_row_major);
            __syncthreads();
        } else {
            __syncthreads();
#pragma unroll
            for (int i = 0; i < 2; ++i)
#pragma unroll
                for (int j = 0; j < 4; ++j)
                    wmma::store_matrix_sync(
                        stage + (size_t)(wm + i * 16) * 128 + wn + j * 16,
                        acc[i][j], 128, wmma::mem_row_major);
            __syncthreads();
#pragma unroll
            for (int it = 0; it < 16; ++it) {
                int idx = it * 256 + t;
                int r = idx >> 5, q = idx & 31;
                float4 v = *reinterpret_cast<const float4*>(stage + (size_t)r * 128 + q * 4);
                float4 bgv = *reinterpret_cast<const float4*>(bg + q * 4);
                float4 o;
                o.x = 1.0f / (1.0f + __expf(-(v.x + bgv.x)));
                o.y = 1.0f / (1.0f + __expf(-(v.y + bgv.y)));
                o.z = 1.0f / (1.0f + __expf(-(v.z + bgv.z)));
                o.w = 1.0f / (1.0f + __expf(-(v.w + bgv.w)));
                *reinterpret_cast<float4*>(g_gate + (size_t)(row0 + r) * D + q * 4) = o;
            }
        }
    }
}

// ============================= attn (WMMA, hi/lo precision) =============================
// Q hi/lo (2-pass QK, K single bf16), P hi/lo & V hi/lo (3-pass PV).
#define LDQ 40
#define LDSS 260
#define LDP2 264
#define LDO 36
#define AQH 0
#define AQL 20480
#define AKB 40960
#define AVH 61440
#define AVL 81920
#define AST 102400
#define APH 135680
#define APL 152576
#define ATTN_SMEM 169472

__global__ void __launch_bounds__(256) attn_wmma_kernel()
{
    extern __shared__ char smem[];
    __nv_bfloat16* Qh = reinterpret_cast<__nv_bfloat16*>(smem + AQH);
    __nv_bfloat16* Ql = reinterpret_cast<__nv_bfloat16*>(smem + AQL);
    __nv_bfloat16* Kb = reinterpret_cast<__nv_bfloat16*>(smem + AKB);
    __nv_bfloat16* Vh = reinterpret_cast<__nv_bfloat16*>(smem + AVH);
    __nv_bfloat16* Vl = reinterpret_cast<__nv_bfloat16*>(smem + AVL);
    float*         St = reinterpret_cast<float*>(smem + AST);            // [k32][j], ld 260
    __nv_bfloat16* Pth = reinterpret_cast<__nv_bfloat16*>(smem + APH);   // [k32][j], ld 264
    __nv_bfloat16* Ptl = reinterpret_cast<__nv_bfloat16*>(smem + APL);
    float*       Sout = reinterpret_cast<float*>(smem + AST);            // reuse: [j][d], ld 36

    const int i = blockIdx.x;
    const int h = blockIdx.y;
    const int t = threadIdx.x;
    const int w = t >> 5;
    const size_t gbase = (size_t)i * 256 * 128 + h * 32;

    // stage q (hi/lo), k (hi), v (hi/lo)
#pragma unroll
    for (int u = 0; u < 8; ++u) {
        int idx = u * 256 + t;
        int row = idx >> 3, c4 = idx & 7;
        size_t goff = gbase + (size_t)row * 128 + c4 * 4;
        size_t soff = (size_t)row * LDQ + c4 * 4;
        float4 q4 = *reinterpret_cast<const float4*>(g_q + goff);
        float4 k4 = *reinterpret_cast<const float4*>(g_k + goff);
        float4 v4 = *reinterpret_cast<const float4*>(g_v + goff);
        __nv_bfloat16 qh0 = bhi(q4.x), qh1 = bhi(q4.y), qh2 = bhi(q4.z), qh3 = bhi(q4.w);
        reinterpret_cast<__nv_bfloat162*>(Qh + soff)[0] = {qh0, qh1};
        reinterpret_cast<__nv_bfloat162*>(Qh + soff)[1] = {qh2, qh3};
        reinterpret_cast<__nv_bfloat162*>(Ql + soff)[0] = {blo(q4.x, qh0), blo(q4.y, qh1)};
        reinterpret_cast<__nv_bfloat162*>(Ql + soff)[1] = {blo(q4.z, qh2), blo(q4.w, qh3)};
        reinterpret_cast<__nv_bfloat162*>(Kb + soff)[0] = {bhi(k4.x), bhi(k4.y)};
        reinterpret_cast<__nv_bfloat162*>(Kb + soff)[1] = {bhi(k4.z), bhi(k4.w)};
        __nv_bfloat16 vh0 = bhi(v4.x), vh1 = bhi(v4.y), vh2 = bhi(v4.z), vh3 = bhi(v4.w);
        reinterpret_cast<__nv_bfloat162*>(Vh + soff)[0] = {vh0, vh1};
        reinterpret_cast<__nv_bfloat162*>(Vh + soff)[1] = {vh2, vh3};
        reinterpret_cast<__nv_bfloat162*>(Vl + soff)[0] = {blo(v4.x, vh0), blo(v4.y, vh1)};
        reinterpret_cast<__nv_bfloat162*>(Vl + soff)[1] = {blo(v4.z, vh2), blo(v4.w, vh3)};
    }
    __syncthreads();

    const float* biasp = g_biasH + (size_t)h * 65536;
    const int j0w = w * 32;

    wmma::fragment<wmma::accumulator, 16, 16, 16, float> acc_o[2][2];
#pragma unroll
    for (int a = 0; a < 2; ++a)
#pragma unroll
        for (int b = 0; b < 2; ++b) wmma::fill_fragment(acc_o[a][b], 0.0f);
    float ssum = 0.0f;

    for (int c = 0; c < 8; ++c) {
        const int k0c = c * 32;

        // ---- S = bias + Qh K^T + Ql K^T ----
        wmma::fragment<wmma::accumulator, 16, 16, 16, float> accs[2][2];
#pragma unroll
        for (int a = 0; a < 2; ++a)
#pragma unroll
            for (int b = 0; b < 2; ++b)
                wmma::load_matrix_sync(accs[a][b],
                    biasp + (size_t)(j0w + a * 16) * 256 + k0c + b * 16,
                    256, wmma::mem_row_major);
#pragma unroll
        for (int s = 0; s < 2; ++s) {
            wmma::fragment<wmma::matrix_a, 16, 16, 16, __nv_bfloat16, wmma::row_major> afh[2], afl[2];
            wmma::load_matrix_sync(afh[0], Qh + (size_t)(j0w +  0) * LDQ + s * 16, LDQ);
            wmma::load_matrix_sync(afh[1], Qh + (size_t)(j0w + 16) * LDQ + s * 16, LDQ);
            wmma::load_matrix_sync(afl[0], Ql + (size_t)(j0w +  0) * LDQ + s * 16, LDQ);
            wmma::load_matrix_sync(afl[1], Ql + (size_t)(j0w + 16) * LDQ + s * 16, LDQ);
#pragma unroll
            for (int b = 0; b < 2; ++b) {
                wmma::fragment<wmma::matrix_b, 16, 16, 16, __nv_bfloat16, wmma::col_major> kf;
                wmma::load_matrix_sync(kf, Kb + (size_t)(k0c + b * 16) * LDQ + s * 16, LDQ);
                wmma::mma_sync(accs[0][b], afh[0], kf, accs[0][b]);
                wmma::mma_sync(accs[1][b], afh[1], kf, accs[1][b]);
                wmma::mma_sync(accs[0][b], afl[0], kf, accs[0][b]);
                wmma::mma_sync(accs[1][b], afl[1], kf, accs[1][b]);
            }
        }
#pragma unroll
        for (int a = 0; a < 2; ++a)
#pragma unroll
            for (int b = 0; b < 2; ++b)
                wmma::store_matrix_sync(St + (size_t)(b * 16) * LDSS + j0w + a * 16,
                                        accs[a][b], LDSS, wmma::mem_col_major);
        __syncthreads();

        // ---- exp: thread t owns row j = t; P split hi/lo ----
#pragma unroll 4
        for (int kk = 0; kk < 32; ++kk) {
            float s = St[(size_t)kk * LDSS + t];
            float p = __expf(s);
            ssum += p;
            __nv_bfloat16 ph = bhi(p);
            Pth[(size_t)kk * LDP2 + t] = ph;
            Ptl[(size_t)kk * LDP2 + t] = blo(p, ph);
        }
        __syncthreads();

        // ---- out += Ph Vh + Pl Vh + Ph Vl ----
#pragma unroll
        for (int s4 = 0; s4 < 2; ++s4) {
            wmma::fragment<wmma::matrix_a, 16, 16, 16, __nv_bfloat16, wmma::col_major> aph[2], apl[2];
            wmma::load_matrix_sync(aph[0], Pth + (size_t)(s4 * 16) * LDP2 + j0w +  0, LDP2);
            wmma::load_matrix_sync(aph[1], Pth + (size_t)(s4 * 16) * LDP2 + j0w + 16, LDP2);
            wmma::load_matrix_sync(apl[0], Ptl + (size_t)(s4 * 16) * LDP2 + j0w +  0, LDP2);
            wmma::load_matrix_sync(apl[1], Ptl + (size_t)(s4 * 16) * LDP2 + j0w + 16, LDP2);
#pragma unroll
            for (int b = 0; b < 2; ++b) {
                wmma::fragment<wmma::matrix_b, 16, 16, 16, __nv_bfloat16, wmma::row_major> vfh, vfl;
                wmma::load_matrix_sync(vfh, Vh + (size_t)(k0c + s4 * 16) * LDQ + b * 16, LDQ);
                wmma::load_matrix_sync(vfl, Vl + (size_t)(k0c + s4 * 16) * LDQ + b * 16, LDQ);
                wmma::mma_sync(acc_o[0][b], aph[0], vfh, acc_o[0][b]);
                wmma::mma_sync(acc_o[1][b], aph[1], vfh, acc_o[1][b]);
                wmma::mma_sync(acc_o[0][b], apl[0], vfh, acc_o[0][b]);
                wmma::mma_sync(acc_o[1][b], apl[1], vfh, acc_o[1][b]);
                wmma::mma_sync(acc_o[0][b], aph[0], vfl, acc_o[0][b]);
                wmma::mma_sync(acc_o[1][b], aph[1], vfl, acc_o[1][b]);
            }
        }
        // no barrier needed here: next chunk's Pt writes are gated by its post-St barrier
    }

    __syncthreads();   // all PV reads of Pt done before Sout overwrites St/Pth region
#pragma unroll
    for (int a = 0; a < 2; ++a)
#pragma unroll
        for (int b = 0; b < 2; ++b)
            wmma::store_matrix_sync(Sout + (size_t)(j0w + a * 16) * LDO + b * 16,
                                    acc_o[a][b], LDO, wmma::mem_row_major);
    __syncthreads();

    float inv = 1.0f / ssum;
    float* op = g_att + gbase + (size_t)t * 128;
#pragma unroll
    for (int d4 = 0; d4 < 8; ++d4) {
        float4 v = *reinterpret_cast<const float4*>(Sout + (size_t)t * LDO + d4 * 4);
        v.x *= inv; v.y *= inv; v.z *= inv; v.w *= inv;
        *reinterpret_cast<float4*>(op + d4 * 4) = v;
    }
}

// ============================= epi (WMMA, hi/lo 3-pass) =============================
#define E_AHI 0
#define E_ALO (128 * 136 * 2)
#define E_BHI (2 * 128 * 136 * 2)
#define E_BLO (E_BHI + 128 * 136 * 2)
#define EPI_SMEM (E_BLO + 128 * 136 * 2)
#define E_STAGE E_AHI

__global__ void __launch_bounds__(256) epi_wmma_kernel(
    const float* __restrict__ bo, float* __restrict__ out)
{
    extern __shared__ char smem[];
    __nv_bfloat16* sAhi = reinterpret_cast<__nv_bfloat16*>(smem + E_AHI);
    __nv_bfloat16* sAlo = reinterpret_cast<__nv_bfloat16*>(smem + E_ALO);
    __nv_bfloat16* sBhi = reinterpret_cast<__nv_bfloat16*>(smem + E_BHI);
    __nv_bfloat16* sBlo = reinterpret_cast<__nv_bfloat16*>(smem + E_BLO);
    float* stage = reinterpret_cast<float*>(smem + E_STAGE);

    const int t = threadIdx.x;
    const int wid = t >> 5;
    const int row0 = blockIdx.x * 128;

#pragma unroll
    for (int it = 0; it < 16; ++it) {
        int idx = it * 256 + t;
        int r = idx >> 5, q = idx & 31;
        size_t off = (size_t)(row0 + r) * D + q * 4;
        float4 g = *reinterpret_cast<const float4*>(g_gate + off);
        float4 a = *reinterpret_cast<const float4*>(g_att + off);
        float4 y = {g.x * a.x, g.y * a.y, g.z * a.z, g.w * a.w};
        __nv_bfloat16 h0 = bhi(y.x), h1 = bhi(y.y), h2 = bhi(y.z), h3 = bhi(y.w);
        size_t soff = (size_t)r * 136 + q * 4;
        reinterpret_cast<__nv_bfloat162*>(sAhi + soff)[0] = {h0, h1};
        reinterpret_cast<__nv_bfloat162*>(sAhi + soff)[1] = {h2, h3};
        reinterpret_cast<__nv_bfloat162*>(sAlo + soff)[0] = {blo(y.x, h0), blo(y.y, h1)};
        reinterpret_cast<__nv_bfloat162*>(sAlo + soff)[1] = {blo(y.z, h2), blo(y.w, h3)};
    }
#pragma unroll
    for (int it = 0; it < 8; ++it) {
        int idx = it * 256 + t;
        int k = idx >> 4, u = idx & 15;
        size_t src = (size_t)k * 128 + u * 8;
        size_t dst = (size_t)k * 136 + u * 8;
        *reinterpret_cast<uint4*>(sBhi + dst) = *reinterpret_cast<const uint4*>(g_Wo_hi + src);
        *reinterpret_cast<uint4*>(sBlo + dst) = *reinterpret_cast<const uint4*>(g_Wo_lo + src);
    }
    __syncthreads();

    const int wm = (wid & 3) * 32;
    const int wn = (wid >> 2) * 64;

    wmma::fragment<wmma::accumulator, 16, 16, 16, float> acc[2][4];
#pragma unroll
    for (int i = 0; i < 2; ++i)
#pragma unroll
        for (int j = 0; j < 4; ++j) wmma::fill_fragment(acc[i][j], 0.0f);

#pragma unroll
    for (int pass = 0; pass < 3; ++pass) {
        const __nv_bfloat16* Ap = (pass == 2) ? sAlo : sAhi;
        const __nv_bfloat16* Bp = (pass == 1) ? sBlo : sBhi;
#pragma unroll
        for (int k8 = 0; k8 < 8; ++k8) {
            wmma::fragment<wmma::matrix_a, 16, 16, 16, __nv_bfloat16, wmma::row_major> af[2];
            wmma::load_matrix_sync(af[0], Ap + (size_t)(wm +  0) * 136 + k8 * 16, 136);
            wmma::load_matrix_sync(af[1], Ap + (size_t)(wm + 16) * 136 + k8 * 16, 136);
            wmma::fragment<wmma::matrix_b, 16, 16, 16, __nv_bfloat16, wmma::row_major> bf;
#pragma unroll
            for (int j = 0; j < 4; ++j) {
                wmma::load_matrix_sync(bf, Bp + (size_t)(k8 * 16) * 136 + wn + j * 16, 136);
                wmma::mma_sync(acc[0][j], af[0], bf, acc[0][j]);
                wmma::mma_sync(acc[1][j], af[1], bf, acc[1][j]);
            }
        }
    }
    __syncthreads();

#pragma unroll
    for (int i = 0; i < 2; ++i)
#pragma unroll
        for (int j = 0; j < 4; ++j)
            wmma::store_matrix_sync(stage + (size_t)(wm + i * 16) * 132 + wn + j * 16,
                                    acc[i][j], 132, wmma::mem_row_major);
    __syncthreads();

#pragma unroll
    for (int it = 0; it < 16; ++it) {
        int idx = it * 256 + t;
        int r = idx >> 5, q = idx & 31;
        float4 v = *reinterpret_cast<const float4*>(stage + (size_t)r * 132 + q * 4);
        float4 b = *reinterpret_cast<const float4*>(bo + q * 4);
        v.x += b.x; v.y += b.y; v.z += b.z; v.w += b.w;
        *reinterpret_cast<float4*>(out + (size_t)(row0 + r) * D + q * 4) = v;
    }
}

extern "C" void kernel_launch(void* const* d_in, const int* in_sizes, int n_in,
                              void* d_out, int out_size)
{
    const float* pair  = (const float*)d_in[0];
    const float* gamma = (const float*)d_in[1];
    const float* beta  = (const float*)d_in[2];
    const float* Wq    = (const float*)d_in[3];
    const float* Wk    = (const float*)d_in[4];
    const float* Wv    = (const float*)d_in[5];
    const float* Wb    = (const float*)d_in[6];
    const float* Wg    = (const float*)d_in[7];
    const float* bg    = (const float*)d_in[8];
    const float* Wo    = (const float*)d_in[9];
    const float* bo    = (const float*)d_in[10];
    float* out = (float*)d_out;

    cudaFuncSetAttribute(proj_wmma_kernel, cudaFuncAttributeMaxDynamicSharedMemorySize, PROJ_SMEM);
    cudaFuncSetAttribute(attn_wmma_kernel, cudaFuncAttributeMaxDynamicSharedMemorySize, ATTN_SMEM);
    cudaFuncSetAttribute(epi_wmma_kernel,  cudaFuncAttributeMaxDynamicSharedMemorySize, EPI_SMEM);

    prep_kernel<<<320, 256>>>(Wq, Wk, Wv, Wg, Wo);
    proj_wmma_kernel<<<(L * L) / 128, 256, PROJ_SMEM>>>(pair, gamma, beta, Wb, bg);
    attn_wmma_kernel<<<dim3(L, H), 256, ATTN_SMEM>>>();
    epi_wmma_kernel<<<(L * L) / 128, 256, EPI_SMEM>>>(bo, out);
}